// round 5
// baseline (speedup 1.0000x reference)
#include <cuda_runtime.h>
#include <cuda_fp16.h>
#include <math.h>

// Problem constants (fixed by the dataset)
#define NB 256      // batch (docs)
#define NL 512      // tokens per doc
#define ND 1024     // embedding dim
#define NV 50001    // emb_table rows
// emb_table is (V+1, D) = (50001, 1024) float32

// Scratch (device globals — no allocation allowed)
__device__ float g_hpart[NB * 2 * ND];   // per-doc 2-way partial sums of emb rows
__device__ float g_v[NB * ND];           // v[b] = W_b @ mean(emb[b])
// fp16 shadow of gathered emb rows: 50001 rows x 256 uint2 chunks (4 halves each)
__device__ uint2 g_ef[(size_t)NV * 256];

// Bit-reinterpret helpers (declared BEFORE first use)
__device__ __forceinline__ unsigned h2_bits(__half2 h) {
    unsigned u;
    memcpy(&u, &h, 4);
    return u;
}

// ---------------------------------------------------------------------------
// Pass 1: partial sums of gathered embedding rows (fp32) + fp16 shadow write.
// Grid: 512 CTAs (2 per doc, 256 tokens each), 256 threads, float4 per thread.
// ---------------------------------------------------------------------------
__global__ void k_hidden(const int* __restrict__ tokens,
                         const float* __restrict__ emb) {
    __shared__ int s_tok[256];
    const int b    = blockIdx.x >> 1;
    const int part = blockIdx.x & 1;
    const int t    = threadIdx.x;

    s_tok[t] = tokens[b * NL + part * 256 + t] + 1;   // +1 per reference lookup
    __syncthreads();

    const float4* emb4 = reinterpret_cast<const float4*>(emb);
    float4 acc = make_float4(0.f, 0.f, 0.f, 0.f);

#pragma unroll 4
    for (int l = 0; l < 256; ++l) {
        const int row = s_tok[l];
        float4 e = __ldg(&emb4[(size_t)row * 256 + t]);
        acc.x += e.x; acc.y += e.y; acc.z += e.z; acc.w += e.w;
        // fp16 shadow (deduplicated by row; duplicate writes are identical)
        uint2 pk;
        pk.x = h2_bits(__floats2half2_rn(e.x, e.y));
        pk.y = h2_bits(__floats2half2_rn(e.z, e.w));
        g_ef[(size_t)row * 256 + t] = pk;
    }
    reinterpret_cast<float4*>(g_hpart)[(b * 2 + part) * 256 + t] = acc;
}

// ---------------------------------------------------------------------------
// Small GEMM (R1 scalar version): v[b,n] = sum_e hidden[b,e] * W[n,e],
// hidden = (p0+p1)/512. M=256, N=1024, K=1024. BM=32, BN=64, BK=32;
// 256 threads; 2x4 microtile. Grid (16, 8) = 128 CTAs.
// ---------------------------------------------------------------------------
__global__ void k_v(const float* __restrict__ W) {
    __shared__ float sA[32 * 34];   // [k][m], pad to 34
    __shared__ float sB[32 * 68];   // [k][n], pad to 68

    const int tid = threadIdx.x;
    const int bn0 = blockIdx.x * 64;
    const int bm0 = blockIdx.y * 32;
    const int tx  = tid & 15;       // n: 4 outputs
    const int ty  = tid >> 4;       // m: 2 outputs
    const int lm  = tid >> 3;       // 0..31
    const int lk  = tid & 7;        // 0..7 float4 groups along k

    const float4* W4  = reinterpret_cast<const float4*>(W);
    const float4* hp4 = reinterpret_cast<const float4*>(g_hpart);

    float acc[2][4] = {{0.f,0.f,0.f,0.f},{0.f,0.f,0.f,0.f}};

    for (int k0 = 0; k0 < 1024; k0 += 32) {
        {
            const int bb = bm0 + lm;
            float4 h0 = hp4[bb * 512 +       (k0 >> 2) + lk];
            float4 h1 = hp4[bb * 512 + 256 + (k0 >> 2) + lk];
            const float s = 1.0f / 512.0f;
            sA[(lk * 4 + 0) * 34 + lm] = (h0.x + h1.x) * s;
            sA[(lk * 4 + 1) * 34 + lm] = (h0.y + h1.y) * s;
            sA[(lk * 4 + 2) * 34 + lm] = (h0.z + h1.z) * s;
            sA[(lk * 4 + 3) * 34 + lm] = (h0.w + h1.w) * s;
        }
#pragma unroll
        for (int r = 0; r < 2; ++r) {
            const int n = lm + r * 32;
            float4 w = W4[(size_t)(bn0 + n) * 256 + (k0 >> 2) + lk];
            sB[(lk * 4 + 0) * 68 + n] = w.x;
            sB[(lk * 4 + 1) * 68 + n] = w.y;
            sB[(lk * 4 + 2) * 68 + n] = w.z;
            sB[(lk * 4 + 3) * 68 + n] = w.w;
        }
        __syncthreads();

#pragma unroll
        for (int k = 0; k < 32; ++k) {
            float2 a2 = *reinterpret_cast<const float2*>(&sA[k * 34 + ty * 2]);
            float4 b4 = *reinterpret_cast<const float4*>(&sB[k * 68 + tx * 4]);
            acc[0][0] += a2.x * b4.x; acc[0][1] += a2.x * b4.y;
            acc[0][2] += a2.x * b4.z; acc[0][3] += a2.x * b4.w;
            acc[1][0] += a2.y * b4.x; acc[1][1] += a2.y * b4.y;
            acc[1][2] += a2.y * b4.z; acc[1][3] += a2.y * b4.w;
        }
        __syncthreads();
    }

#pragma unroll
    for (int i = 0; i < 2; ++i) {
        const int row = bm0 + ty * 2 + i;
        float4 o = make_float4(acc[i][0], acc[i][1], acc[i][2], acc[i][3]);
        reinterpret_cast<float4*>(g_v)[row * 256 + (bn0 >> 2) + tx] = o;
    }
}

// ---------------------------------------------------------------------------
// Pass 2: per-doc online softmax + weighted context, reading the fp16 shadow.
// 1 CTA per doc, 512 threads = 16 warps, each warp owns 32 tokens with a
// warp-private (m, den, n[1024]) flash state; cross-warp combine via SMEM.
// ---------------------------------------------------------------------------
__global__ void __launch_bounds__(512, 1)
k_ct(const int* __restrict__ tokens, float* __restrict__ out) {
    __shared__ int   s_tok[512];
    __shared__ float s_ct[1024];
    __shared__ float s_m[16];
    __shared__ float s_d[16];

    const int b    = blockIdx.x;
    const int tid  = threadIdx.x;
    const int w    = tid >> 5;
    const int lane = tid & 31;

    s_tok[tid]       = tokens[b * NL + tid] + 1;
    s_ct[tid]        = 0.f;
    s_ct[tid + 512]  = 0.f;
    __syncthreads();

    const float4* v4 = reinterpret_cast<const float4*>(g_v);

    // lane owns D-components d = it*128 + lane*4 .. +3, it = 0..7
    float4 vr[8];
#pragma unroll
    for (int it = 0; it < 8; ++it) vr[it] = v4[b * 256 + it * 32 + lane];

    float4 nacc[8];
#pragma unroll
    for (int it = 0; it < 8; ++it) nacc[it] = make_float4(0.f, 0.f, 0.f, 0.f);

    float m   = -INFINITY;
    float den = 0.f;

    for (int j = 0; j < 32; ++j) {
        const int row = s_tok[w * 32 + j];
        const uint2* p = &g_ef[(size_t)row * 256] + lane;

        float4 e[8];
        float  s = 0.f;
#pragma unroll
        for (int it = 0; it < 8; ++it) {
            uint2 q = __ldg(&p[it * 32]);
            __half2 h01, h23;
            memcpy(&h01, &q.x, 4);
            memcpy(&h23, &q.y, 4);
            float2 f01 = __half22float2(h01);
            float2 f23 = __half22float2(h23);
            e[it] = make_float4(f01.x, f01.y, f23.x, f23.y);
            s += e[it].x * vr[it].x + e[it].y * vr[it].y
               + e[it].z * vr[it].z + e[it].w * vr[it].w;
        }
#pragma unroll
        for (int o = 16; o; o >>= 1) s += __shfl_xor_sync(0xffffffffu, s, o);

        const float m_new = fmaxf(m, s);
        const float c  = __expf(m - m_new);   // 1 when max unchanged, 0 on first
        const float wl = __expf(s - m_new);
        den = den * c + wl;
        if (c != 1.0f) {
#pragma unroll
            for (int it = 0; it < 8; ++it) {
                nacc[it].x *= c; nacc[it].y *= c;
                nacc[it].z *= c; nacc[it].w *= c;
            }
        }
#pragma unroll
        for (int it = 0; it < 8; ++it) {
            nacc[it].x += wl * e[it].x; nacc[it].y += wl * e[it].y;
            nacc[it].z += wl * e[it].z; nacc[it].w += wl * e[it].w;
        }
        m = m_new;
    }

    if (lane == 0) { s_m[w] = m; s_d[w] = den; }
    __syncthreads();

    float M = -INFINITY;
#pragma unroll
    for (int i = 0; i < 16; ++i) M = fmaxf(M, s_m[i]);
    float dg = 0.f;
#pragma unroll
    for (int i = 0; i < 16; ++i) dg += s_d[i] * __expf(s_m[i] - M);

    const float sc = __expf(m - M) / dg;
#pragma unroll
    for (int it = 0; it < 8; ++it) {
        const int d0 = it * 128 + lane * 4;
        atomicAdd(&s_ct[d0 + 0], nacc[it].x * sc);
        atomicAdd(&s_ct[d0 + 1], nacc[it].y * sc);
        atomicAdd(&s_ct[d0 + 2], nacc[it].z * sc);
        atomicAdd(&s_ct[d0 + 3], nacc[it].w * sc);
    }
    __syncthreads();

    out[b * ND + tid]       = s_ct[tid];
    out[b * ND + tid + 512] = s_ct[tid + 512];
}

// ---------------------------------------------------------------------------
extern "C" void kernel_launch(void* const* d_in, const int* in_sizes, int n_in,
                              void* d_out, int out_size) {
    const int*   tokens = (const int*)d_in[0];
    // d_in[1] = max_len (scalar, unused — fixed at 512)
    const float* emb    = (const float*)d_in[2];
    const float* W      = (const float*)d_in[3];
    float*       out    = (float*)d_out;

    k_hidden<<<NB * 2, 256>>>(tokens, emb);
    k_v<<<dim3(16, 8), 256>>>(W);
    k_ct<<<NB, 512>>>(tokens, out);
}

// round 6
// speedup vs baseline: 1.3819x; 1.3819x over previous
#include <cuda_runtime.h>
#include <math.h>

// Problem constants (fixed by the dataset)
#define NB 256      // batch (docs)
#define NL 512      // tokens per doc
#define ND 1024     // embedding dim
// emb_table is (V+1, D) = (50001, 1024) float32

// Scratch (device globals — no allocation allowed)
__device__ float g_hpart[NB * 2 * ND];  // per-doc 2-way partial sums of emb rows
__device__ float g_v[NB * ND];          // v[b] = W_b @ mean(emb[b])

// ---------------------------------------------------------------------------
// Pass 1: partial sums of gathered embedding rows.  (EXACT R1 version)
// Grid: 512 CTAs (2 per doc, 256 tokens each), 256 threads, float4 per thread.
// ---------------------------------------------------------------------------
__global__ void k_hidden(const int* __restrict__ tokens,
                         const float* __restrict__ emb) {
    __shared__ int s_tok[256];
    const int b    = blockIdx.x >> 1;
    const int part = blockIdx.x & 1;
    const int t    = threadIdx.x;

    s_tok[t] = tokens[b * NL + part * 256 + t] + 1;   // +1 per reference lookup
    __syncthreads();

    const float4* emb4 = reinterpret_cast<const float4*>(emb);
    float4 acc = make_float4(0.f, 0.f, 0.f, 0.f);

#pragma unroll 4
    for (int l = 0; l < 256; ++l) {
        const int row = s_tok[l];
        float4 e = __ldg(&emb4[(size_t)row * 256 + t]);
        acc.x += e.x; acc.y += e.y; acc.z += e.z; acc.w += e.w;
    }
    reinterpret_cast<float4*>(g_hpart)[(b * 2 + part) * 256 + t] = acc;
}

// ---------------------------------------------------------------------------
// Small GEMM (R1 scalar): v[b,n] = sum_e hidden[b,e] * W[n,e],
// hidden = (p0+p1)/512.  M=256, N=1024, K=1024.  BM=32, BN=64, BK=32;
// 256 threads; 2x4 microtile. Grid (16, 8) = 128 CTAs.
// ---------------------------------------------------------------------------
__global__ void k_v(const float* __restrict__ W) {
    __shared__ float sA[32 * 34];   // [k][m], pad to 34
    __shared__ float sB[32 * 68];   // [k][n], pad to 68

    const int tid = threadIdx.x;
    const int bn0 = blockIdx.x * 64;
    const int bm0 = blockIdx.y * 32;
    const int tx  = tid & 15;       // n: 4 outputs
    const int ty  = tid >> 4;       // m: 2 outputs
    const int lm  = tid >> 3;       // 0..31
    const int lk  = tid & 7;        // 0..7 float4 groups along k

    const float4* W4  = reinterpret_cast<const float4*>(W);
    const float4* hp4 = reinterpret_cast<const float4*>(g_hpart);

    float acc[2][4] = {{0.f,0.f,0.f,0.f},{0.f,0.f,0.f,0.f}};

    for (int k0 = 0; k0 < 1024; k0 += 32) {
        {
            const int bb = bm0 + lm;
            float4 h0 = hp4[bb * 512 +       (k0 >> 2) + lk];
            float4 h1 = hp4[bb * 512 + 256 + (k0 >> 2) + lk];
            const float s = 1.0f / 512.0f;
            sA[(lk * 4 + 0) * 34 + lm] = (h0.x + h1.x) * s;
            sA[(lk * 4 + 1) * 34 + lm] = (h0.y + h1.y) * s;
            sA[(lk * 4 + 2) * 34 + lm] = (h0.z + h1.z) * s;
            sA[(lk * 4 + 3) * 34 + lm] = (h0.w + h1.w) * s;
        }
#pragma unroll
        for (int r = 0; r < 2; ++r) {
            const int n = lm + r * 32;
            float4 w = W4[(size_t)(bn0 + n) * 256 + (k0 >> 2) + lk];
            sB[(lk * 4 + 0) * 68 + n] = w.x;
            sB[(lk * 4 + 1) * 68 + n] = w.y;
            sB[(lk * 4 + 2) * 68 + n] = w.z;
            sB[(lk * 4 + 3) * 68 + n] = w.w;
        }
        __syncthreads();

#pragma unroll
        for (int k = 0; k < 32; ++k) {
            float2 a2 = *reinterpret_cast<const float2*>(&sA[k * 34 + ty * 2]);
            float4 b4 = *reinterpret_cast<const float4*>(&sB[k * 68 + tx * 4]);
            acc[0][0] += a2.x * b4.x; acc[0][1] += a2.x * b4.y;
            acc[0][2] += a2.x * b4.z; acc[0][3] += a2.x * b4.w;
            acc[1][0] += a2.y * b4.x; acc[1][1] += a2.y * b4.y;
            acc[1][2] += a2.y * b4.z; acc[1][3] += a2.y * b4.w;
        }
        __syncthreads();
    }

#pragma unroll
    for (int i = 0; i < 2; ++i) {
        const int row = bm0 + ty * 2 + i;
        float4 o = make_float4(acc[i][0], acc[i][1], acc[i][2], acc[i][3]);
        reinterpret_cast<float4*>(g_v)[row * 256 + (bn0 >> 2) + tx] = o;
    }
}

// ---------------------------------------------------------------------------
// Pass 2: per-doc online softmax + weighted context — split-D warp pairs.
// 1 CTA/doc, 512 thr = 16 warps = 8 pairs. Pair p handles tokens p*64..+63;
// warp half h accumulates D-half h (512 floats, 4 float4 per lane).
// Per-token full-D score via smem exchange + named barrier (id p+1, 64 thr).
// 2 CTAs/SM -> all 256 CTAs in one wave, 32 warps/SM.
// ---------------------------------------------------------------------------
__global__ void __launch_bounds__(512, 2)
k_ct(const int* __restrict__ tokens, const float* __restrict__ emb,
     float* __restrict__ out) {
    __shared__ int   s_tok[512];
    __shared__ float s_ct[1024];
    __shared__ float s_ex[8][2][2];   // [pair][token parity][half]
    __shared__ float s_m[8];
    __shared__ float s_d[8];

    const int b    = blockIdx.x;
    const int tid  = threadIdx.x;
    const int w    = tid >> 5;
    const int p    = w >> 1;          // pair 0..7
    const int h    = w & 1;           // D-half 0/1
    const int lane = tid & 31;

    s_tok[tid]      = tokens[b * NL + tid] + 1;
    s_ct[tid]       = 0.f;
    s_ct[tid + 512] = 0.f;
    __syncthreads();

    const float4* emb4 = reinterpret_cast<const float4*>(emb);
    const float4* v4   = reinterpret_cast<const float4*>(g_v);

    // lane owns D-components d = h*512 + it*128 + lane*4 .. +3, it = 0..3
    float4 vr[4];
#pragma unroll
    for (int it = 0; it < 4; ++it) vr[it] = v4[b * 256 + h * 128 + it * 32 + lane];

    float4 nacc[4];
#pragma unroll
    for (int it = 0; it < 4; ++it) nacc[it] = make_float4(0.f, 0.f, 0.f, 0.f);

    float m   = -INFINITY;
    float den = 0.f;

    for (int j = 0; j < 64; ++j) {
        const int row = s_tok[p * 64 + j];
        const float4* q = emb4 + (size_t)row * 256 + h * 128 + lane;

        float4 e[4];
        float  s = 0.f;
#pragma unroll
        for (int it = 0; it < 4; ++it) {
            e[it] = q[it * 32];
            s += e[it].x * vr[it].x + e[it].y * vr[it].y
               + e[it].z * vr[it].z + e[it].w * vr[it].w;
        }
#pragma unroll
        for (int o = 16; o; o >>= 1) s += __shfl_xor_sync(0xffffffffu, s, o);

        if (lane == 0) s_ex[p][j & 1][h] = s;
        asm volatile("bar.sync %0, 64;" :: "r"(p + 1) : "memory");
        s = s_ex[p][j & 1][0] + s_ex[p][j & 1][1];

        const float m_new = fmaxf(m, s);
        const float c  = __expf(m - m_new);   // 1 when max unchanged, 0 on first
        const float wl = __expf(s - m_new);
        den = den * c + wl;
        if (c != 1.0f) {
#pragma unroll
            for (int it = 0; it < 4; ++it) {
                nacc[it].x *= c; nacc[it].y *= c;
                nacc[it].z *= c; nacc[it].w *= c;
            }
        }
#pragma unroll
        for (int it = 0; it < 4; ++it) {
            nacc[it].x += wl * e[it].x; nacc[it].y += wl * e[it].y;
            nacc[it].z += wl * e[it].z; nacc[it].w += wl * e[it].w;
        }
        m = m_new;
    }

    // per-pair state (identical in both halves of a pair)
    if (h == 0 && lane == 0) { s_m[p] = m; s_d[p] = den; }
    __syncthreads();

    float M = -INFINITY;
#pragma unroll
    for (int i = 0; i < 8; ++i) M = fmaxf(M, s_m[i]);
    float dg = 0.f;
#pragma unroll
    for (int i = 0; i < 8; ++i) dg += s_d[i] * __expf(s_m[i] - M);

    const float sc = __expf(m - M) / dg;
#pragma unroll
    for (int it = 0; it < 4; ++it) {
        const int d0 = h * 512 + it * 128 + lane * 4;
        atomicAdd(&s_ct[d0 + 0], nacc[it].x * sc);
        atomicAdd(&s_ct[d0 + 1], nacc[it].y * sc);
        atomicAdd(&s_ct[d0 + 2], nacc[it].z * sc);
        atomicAdd(&s_ct[d0 + 3], nacc[it].w * sc);
    }
    __syncthreads();

    out[b * ND + tid]       = s_ct[tid];
    out[b * ND + tid + 512] = s_ct[tid + 512];
}

// ---------------------------------------------------------------------------
extern "C" void kernel_launch(void* const* d_in, const int* in_sizes, int n_in,
                              void* d_out, int out_size) {
    const int*   tokens = (const int*)d_in[0];
    // d_in[1] = max_len (scalar, unused — fixed at 512)
    const float* emb    = (const float*)d_in[2];
    const float* W      = (const float*)d_in[3];
    float*       out    = (float*)d_out;

    k_hidden<<<NB * 2, 256>>>(tokens, emb);
    k_v<<<dim3(16, 8), 256>>>(W);
    k_ct<<<NB, 512>>>(tokens, emb, out);
}